// round 7
// baseline (speedup 1.0000x reference)
#include <cuda_runtime.h>
#include <cuda_bf16.h>
#include <cstdint>

// ---------------- problem-size constants (fixed by the dataset) -------------
#define MAXN 100000
#define MAXE 1600000

// ---------------- device scratch (allocation-free rule: __device__ globals) -
// All buffers accessed with float4/float2 vector loads MUST be 16B-aligned.
__device__ __align__(16) float g_Y [MAXN * 192];   // [y1 | y2 | y0] after GEMM1
__device__ __align__(16) float g_U [MAXN * 64];    // u = y1 + 2*L y2
__device__ __align__(16) float g_H2[MAXN * 192];   // [h1 | t1 | t2] for layer 2
__device__ __align__(16) float g_H3[MAXN * 384];   // [h2 | t1 | t2] for layer 3
__device__ __align__(16) float g_Wcat[128 * 192];  // [W1_1 | W1_2 | W1_0 - W1_2]

__device__ float g_dinv[MAXN];
__device__ int   g_deg [MAXN];
__device__ int   g_cnt [MAXN];
__device__ int   g_cur [MAXN];
__device__ int   g_rowstart[MAXN];
__device__ int   g_blocksums[256];
__device__ int   g_csr_src[MAXE];
__device__ float g_csr_w [MAXE];
__device__ int   g_is64;          // 1 if edge_index is int64, 0 if int32

// ---------------- packed f32x2 helpers (sm_103a) ----------------------------
__device__ __forceinline__ unsigned long long pack2(float x, float y) {
    unsigned long long r;
    asm("mov.b64 %0, {%1, %2};" : "=l"(r) : "f"(x), "f"(y));
    return r;
}
__device__ __forceinline__ float2 unpack2(unsigned long long v) {
    float2 r;
    asm("mov.b64 {%0, %1}, %2;" : "=f"(r.x), "=f"(r.y) : "l"(v));
    return r;
}
__device__ __forceinline__ void fma2(unsigned long long& d,
                                     unsigned long long a,
                                     unsigned long long b) {
    asm("fma.rn.f32x2 %0, %1, %2, %3;" : "=l"(d) : "l"(a), "l"(b), "l"(d));
}

// ---------------- edge dtype detection + access -----------------------------
// JAX default config disables x64, so the "int64" edge_index is most likely
// int32 on disk. Detect at runtime: genuine int64 little-endian values
// < 2^31 have zero high words; packed int32 data has random node ids there.
__global__ void detect_kernel(const int* __restrict__ ei32, int E) {
    if (threadIdx.x == 0 && blockIdx.x == 0) {
        int is64 = 1;
        int nchk = (E < 64) ? E : 64;
        for (int i = 0; i < nchk; i++) {
            if (ei32[2 * i + 1] != 0) { is64 = 0; break; }
        }
        g_is64 = is64;
    }
}

__device__ __forceinline__ void load_edge(const void* ei, int e, int E, int is64,
                                          int& s, int& d) {
    if (is64) {
        const long long* p = (const long long*)ei;
        s = (int)p[e];
        d = (int)p[E + e];
    } else {
        const int* p = (const int*)ei;
        s = p[e];
        d = p[E + e];
    }
}

// ---------------- small setup kernels --------------------------------------
__global__ void init_kernel(int N) {
    int i = blockIdx.x * blockDim.x + threadIdx.x;
    if (i < N) { g_deg[i] = 0; g_cnt[i] = 0; g_cur[i] = 0; }
}

__global__ void deg_cnt_kernel(const void* __restrict__ ei, int E) {
    int e = blockIdx.x * blockDim.x + threadIdx.x;
    if (e >= E) return;
    int is64 = g_is64;
    int s, d;
    load_edge(ei, e, E, is64, s, d);
    if (s != d) {
        atomicAdd(&g_deg[s], 1);
        atomicAdd(&g_cnt[d], 1);
    }
}

__global__ void dinv_kernel(int N) {
    int i = blockIdx.x * blockDim.x + threadIdx.x;
    if (i >= N) return;
    int dg = g_deg[i];
    g_dinv[i] = (dg > 0) ? rsqrtf((float)dg) : 0.0f;
}

// exclusive prefix sum of g_cnt -> g_rowstart (3-kernel scan)
__global__ void scan1_kernel(int N) {
    __shared__ int sm[1024];
    int t = threadIdx.x;
    int i = blockIdx.x * 1024 + t;
    int v = (i < N) ? g_cnt[i] : 0;
    sm[t] = v;
    __syncthreads();
    for (int off = 1; off < 1024; off <<= 1) {
        int x = (t >= off) ? sm[t - off] : 0;
        __syncthreads();
        sm[t] += x;
        __syncthreads();
    }
    if (i < N) g_rowstart[i] = sm[t] - v;
    if (t == 1023) g_blocksums[blockIdx.x] = sm[1023];
}

__global__ void scan2_kernel(int nb) {
    if (threadIdx.x == 0 && blockIdx.x == 0) {
        int run = 0;
        for (int i = 0; i < nb; i++) {
            int t = g_blocksums[i];
            g_blocksums[i] = run;
            run += t;
        }
    }
}

__global__ void scan3_kernel(int N) {
    int i = blockIdx.x * 1024 + threadIdx.x;
    if (i < N) g_rowstart[i] += g_blocksums[blockIdx.x];
}

__global__ void fill_kernel(const void* __restrict__ ei, int E) {
    int e = blockIdx.x * blockDim.x + threadIdx.x;
    if (e >= E) return;
    int is64 = g_is64;
    int s, d;
    load_edge(ei, e, E, is64, s, d);
    if (s != d) {
        float w = -g_dinv[s] * g_dinv[d];
        int p = g_rowstart[d] + atomicAdd(&g_cur[d], 1);
        g_csr_src[p] = s;
        g_csr_w[p]   = w;
    }
}

// Wcat = [W1[1] | W1[2] | W1[0]-W1[2]]   (128 x 192)
__global__ void wcat_kernel(const float* __restrict__ W1, float* __restrict__ Wc) {
    int idx = blockIdx.x * blockDim.x + threadIdx.x;
    if (idx >= 128 * 192) return;
    int i = idx / 192, j = idx % 192;
    float v;
    if (j < 64)        v = W1[8192     + i * 64 + j];
    else if (j < 128)  v = W1[2 * 8192 + i * 64 + (j - 64)];
    else               v = W1[           i * 64 + (j - 128)]
                         - W1[2 * 8192 + i * 64 + (j - 128)];
    Wc[idx] = v;
}

// ---------------- GEMM: C[M,N] = A[M,K] @ B[K,N] (+bias)(+relu) -------------
// BM=128, BN=64, BK=32; 256 threads; per-thread 8x4 via packed fma.rn.f32x2.
// Requires: K % 32 == 0, N % 64 == 0 (true for all call sites).
__global__ __launch_bounds__(256) void gemm_kernel(
    const float* __restrict__ A, int lda,
    const float* __restrict__ B, int ldb,
    float* __restrict__ C, int ldc,
    int M, int N, int K,
    const float* __restrict__ bias, int do_relu)
{
    // LDS.128 reads below require 16B-aligned bases.
    __shared__ __align__(16) float As[32][132];              // transposed, padded
    __shared__ __align__(16) unsigned long long Bsd[32][64]; // B duplicated {b,b}

    int tid = threadIdx.x;
    int tx = tid & 15;        // col group: cols tx*4 .. +3
    int ty = tid >> 4;        // row group: rows ty*8 .. +7
    int m0 = blockIdx.y * 128;
    int n0 = blockIdx.x * 64;

    unsigned long long acc[4][4];
#pragma unroll
    for (int i = 0; i < 4; i++)
#pragma unroll
        for (int j = 0; j < 4; j++) acc[i][j] = 0ull;

    for (int kt = 0; kt < K; kt += 32) {
        // A tile load: 128x32, float4 along K, store transposed
#pragma unroll
        for (int i = 0; i < 4; i++) {
            int f = tid + i * 256;
            int m = f >> 3;
            int kk = (f & 7) << 2;
            float4 v = make_float4(0.f, 0.f, 0.f, 0.f);
            int row = m0 + m;
            if (row < M)
                v = *reinterpret_cast<const float4*>(A + (size_t)row * lda + kt + kk);
            As[kk + 0][m] = v.x;
            As[kk + 1][m] = v.y;
            As[kk + 2][m] = v.z;
            As[kk + 3][m] = v.w;
        }
        // B tile load: 32x64, duplicate each value into {b,b}
#pragma unroll
        for (int i = 0; i < 2; i++) {
            int f = tid + i * 256;
            int k = f >> 4;
            int nn = (f & 15) << 2;
            float4 v = *reinterpret_cast<const float4*>(B + (size_t)(kt + k) * ldb + n0 + nn);
            Bsd[k][nn + 0] = pack2(v.x, v.x);
            Bsd[k][nn + 1] = pack2(v.y, v.y);
            Bsd[k][nn + 2] = pack2(v.z, v.z);
            Bsd[k][nn + 3] = pack2(v.w, v.w);
        }
        __syncthreads();
#pragma unroll
        for (int k = 0; k < 32; k++) {
            ulonglong2 a01 = *reinterpret_cast<const ulonglong2*>(&As[k][ty << 3]);
            ulonglong2 a23 = *reinterpret_cast<const ulonglong2*>(&As[k][(ty << 3) + 4]);
            ulonglong2 b01 = *reinterpret_cast<const ulonglong2*>(&Bsd[k][tx << 2]);
            ulonglong2 b23 = *reinterpret_cast<const ulonglong2*>(&Bsd[k][(tx << 2) + 2]);
            unsigned long long ar[4] = {a01.x, a01.y, a23.x, a23.y};
            unsigned long long br[4] = {b01.x, b01.y, b23.x, b23.y};
#pragma unroll
            for (int i = 0; i < 4; i++)
#pragma unroll
                for (int j = 0; j < 4; j++)
                    fma2(acc[i][j], ar[i], br[j]);
        }
        __syncthreads();
    }

    float bb[4];
#pragma unroll
    for (int j = 0; j < 4; j++)
        bb[j] = bias ? bias[n0 + (tx << 2) + j] : 0.f;

#pragma unroll
    for (int i = 0; i < 4; i++) {
        int row = m0 + (ty << 3) + 2 * i;
        float4 lo4, hi4;
        float* lop = &lo4.x;
        float* hip = &hi4.x;
#pragma unroll
        for (int j = 0; j < 4; j++) {
            float2 v = unpack2(acc[i][j]);
            float a = v.x + bb[j];
            float b = v.y + bb[j];
            if (do_relu) { a = fmaxf(a, 0.f); b = fmaxf(b, 0.f); }
            lop[j] = a;
            hip[j] = b;
        }
        if (row < M)
            *reinterpret_cast<float4*>(C + (size_t)row * ldc + n0 + (tx << 2)) = lo4;
        if (row + 1 < M)
            *reinterpret_cast<float4*>(C + (size_t)(row + 1) * ldc + n0 + (tx << 2)) = hi4;
    }
}

// ---------------- propagation: out = alpha*(L @ in) + beta*add + bias, relu -
// One warp per destination node; CSR gather; vectorized loads.
__device__ __forceinline__ void accum4(float* acc, const float* p, float w) {
    float4 r = *reinterpret_cast<const float4*>(p);
    acc[0] = fmaf(w, r.x, acc[0]);
    acc[1] = fmaf(w, r.y, acc[1]);
    acc[2] = fmaf(w, r.z, acc[2]);
    acc[3] = fmaf(w, r.w, acc[3]);
}
__device__ __forceinline__ void accum2(float* acc, const float* p, float w) {
    float2 r = *reinterpret_cast<const float2*>(p);
    acc[0] = fmaf(w, r.x, acc[0]);
    acc[1] = fmaf(w, r.y, acc[1]);
}

template <int C>
__global__ __launch_bounds__(256) void prop_kernel(
    const float* __restrict__ in, int in_stride,
    float* __restrict__ out, int out_stride,
    const float* __restrict__ add, int add_stride,
    float alpha, float beta,
    const float* __restrict__ bias, int do_relu, int Nn)
{
    constexpr int V = C / 32;
    int gw = (blockIdx.x * blockDim.x + threadIdx.x) >> 5;
    int lane = threadIdx.x & 31;
    if (gw >= Nn) return;

    int start = g_rowstart[gw];
    int cnt = g_cnt[gw];
    float acc[V];
#pragma unroll
    for (int v = 0; v < V; v++) acc[v] = 0.f;

    const int feat = lane * V;
    int e = 0;
    for (; e + 4 <= cnt; e += 4) {
        int s0 = g_csr_src[start + e + 0];
        int s1 = g_csr_src[start + e + 1];
        int s2 = g_csr_src[start + e + 2];
        int s3 = g_csr_src[start + e + 3];
        float w0 = g_csr_w[start + e + 0];
        float w1 = g_csr_w[start + e + 1];
        float w2 = g_csr_w[start + e + 2];
        float w3 = g_csr_w[start + e + 3];
        const float* p0 = in + (size_t)s0 * in_stride + feat;
        const float* p1 = in + (size_t)s1 * in_stride + feat;
        const float* p2 = in + (size_t)s2 * in_stride + feat;
        const float* p3 = in + (size_t)s3 * in_stride + feat;
        if (V == 4) {
            accum4(acc, p0, w0); accum4(acc, p1, w1);
            accum4(acc, p2, w2); accum4(acc, p3, w3);
        } else {
            accum2(acc, p0, w0); accum2(acc, p1, w1);
            accum2(acc, p2, w2); accum2(acc, p3, w3);
        }
    }
    for (; e < cnt; e++) {
        int s = g_csr_src[start + e];
        float w = g_csr_w[start + e];
        const float* p = in + (size_t)s * in_stride + feat;
        if (V == 4) accum4(acc, p, w);
        else        accum2(acc, p, w);
    }

    float res[V];
#pragma unroll
    for (int v = 0; v < V; v++) res[v] = alpha * acc[v];
    if (add) {
        const float* ap = add + (size_t)gw * add_stride + feat;
        if (V == 4) {
            float4 a = *reinterpret_cast<const float4*>(ap);
            res[0] = fmaf(beta, a.x, res[0]);
            res[1] = fmaf(beta, a.y, res[1]);
            res[2] = fmaf(beta, a.z, res[2]);
            res[3] = fmaf(beta, a.w, res[3]);
        } else {
            float2 a = *reinterpret_cast<const float2*>(ap);
            res[0] = fmaf(beta, a.x, res[0]);
            res[1] = fmaf(beta, a.y, res[1]);
        }
    }
    if (bias) {
#pragma unroll
        for (int v = 0; v < V; v++) res[v] += bias[feat + v];
    }
    if (do_relu) {
#pragma unroll
        for (int v = 0; v < V; v++) res[v] = fmaxf(res[v], 0.f);
    }
    float* op = out + (size_t)gw * out_stride + feat;
    if (V == 4) {
        float4 o = make_float4(res[0], res[1], res[2], res[3]);
        *reinterpret_cast<float4*>(op) = o;
    } else {
        float2 o = make_float2(res[0], res[1]);
        *reinterpret_cast<float2*>(op) = o;
    }
}

// ---------------- launch ----------------------------------------------------
extern "C" void kernel_launch(void* const* d_in, const int* in_sizes, int n_in,
                              void* d_out, int out_size)
{
    const float* x  = (const float*)d_in[0];
    const void*  ei = d_in[1];
    const float* W1 = (const float*)d_in[3];
    const float* b1 = (const float*)d_in[4];
    const float* W2 = (const float*)d_in[5];
    const float* b2 = (const float*)d_in[6];
    const float* W3 = (const float*)d_in[7];
    const float* b3 = (const float*)d_in[8];

    int N = in_sizes[2];      // batch vector has N entries
    int E = in_sizes[1] / 2;

    float *Y, *U, *H2, *H3, *Wc;
    cudaGetSymbolAddress((void**)&Y,  g_Y);
    cudaGetSymbolAddress((void**)&U,  g_U);
    cudaGetSymbolAddress((void**)&H2, g_H2);
    cudaGetSymbolAddress((void**)&H3, g_H3);
    cudaGetSymbolAddress((void**)&Wc, g_Wcat);

    int nblk = (N + 255) / 256;
    int eblk = (E + 255) / 256;
    int nb1024 = (N + 1023) / 1024;
    int pblk = (N + 7) / 8;   // 8 warps / block
    int mgrid = (N + 127) / 128;

    // ---- graph normalization + CSR build ----
    detect_kernel<<<1, 32>>>((const int*)ei, E);
    init_kernel<<<nblk, 256>>>(N);
    deg_cnt_kernel<<<eblk, 256>>>(ei, E);
    dinv_kernel<<<nblk, 256>>>(N);
    scan1_kernel<<<nb1024, 1024>>>(N);
    scan2_kernel<<<1, 32>>>(nb1024);
    scan3_kernel<<<nb1024, 1024>>>(N);
    fill_kernel<<<eblk, 256>>>(ei, E);

    // ---- layer 1 (output-space propagation):
    // out1 = relu( x(W0-W2) + L(xW1 + 2 L(xW2)) + b1 )
    wcat_kernel<<<(128 * 192 + 255) / 256, 256>>>(W1, Wc);
    {   // Y = x @ [W1_1 | W1_2 | W1_0 - W1_2]    (100k x 192)
        dim3 g(192 / 64, mgrid);
        gemm_kernel<<<g, 256>>>(x, 128, Wc, 192, Y, 192, N, 192, 128, nullptr, 0);
    }
    // U = y1 + 2 * (L @ y2)
    prop_kernel<64><<<pblk, 256>>>(Y + 64, 192, U, 64, Y, 192, 2.f, 1.f, nullptr, 0, N);
    // H2[:,0:64] = relu( (L @ U) + y0 + b1 )
    prop_kernel<64><<<pblk, 256>>>(U, 64, H2, 192, Y + 128, 192, 1.f, 1.f, b1, 1, N);

    // ---- layer 2 (input-space propagation) ----
    // t1 = L h1 ; t2 = 2 L t1 - h1 ; out2 = relu([h1|t1|t2] @ W2 + b2)
    prop_kernel<64><<<pblk, 256>>>(H2, 192, H2 + 64, 192, nullptr, 0, 1.f, 0.f, nullptr, 0, N);
    prop_kernel<64><<<pblk, 256>>>(H2 + 64, 192, H2 + 128, 192, H2, 192, 2.f, -1.f, nullptr, 0, N);
    {
        dim3 g(128 / 64, mgrid);
        gemm_kernel<<<g, 256>>>(H2, 192, W2, 128, H3, 384, N, 128, 192, b2, 1);
    }

    // ---- layer 3 ----
    prop_kernel<128><<<pblk, 256>>>(H3, 384, H3 + 128, 384, nullptr, 0, 1.f, 0.f, nullptr, 0, N);
    prop_kernel<128><<<pblk, 256>>>(H3 + 128, 384, H3 + 256, 384, H3, 384, 2.f, -1.f, nullptr, 0, N);
    {
        dim3 g(256 / 64, mgrid);
        gemm_kernel<<<g, 256>>>(H3, 384, W3, 256, (float*)d_out, 256, N, 256, 384, b3, 0);
    }
}